// round 3
// baseline (speedup 1.0000x reference)
#include <cuda_runtime.h>

#define N_NODES 50000
#define IN_DIM  512
#define HDIM    2048
#define OUT_DIM 512

// Scratch buffers (device globals: allocation-free scratch per harness rules)
__device__ float g_h [(size_t)N_NODES * (2 * IN_DIM)];  // concat [x, agg]  (~205 MB)
__device__ float g_h1[(size_t)N_NODES * HDIM];          // relu(h @ W1 + b1) (~410 MB)
__device__ float g_h2[(size_t)N_NODES * HDIM];          // relu(h1 @ W2 + b2) (~410 MB)

// ---------------------------------------------------------------------------
// Kernel 1: build h = [x, 0] (left half copy of x, right half zeroed for the
// subsequent atomic scatter-add). float4 granularity.
// ---------------------------------------------------------------------------
__global__ void init_h_kernel(const float* __restrict__ x, int n)
{
    long long i = (long long)blockIdx.x * blockDim.x + threadIdx.x;
    long long total = (long long)n * 256;   // 1024 floats per row = 256 float4
    if (i >= total) return;
    int row = (int)(i >> 8);
    int c4  = (int)(i & 255);
    float4 v = make_float4(0.f, 0.f, 0.f, 0.f);
    if (c4 < 128)
        v = ((const float4*)x)[(long long)row * 128 + c4];
    ((float4*)g_h)[i] = v;
}

// ---------------------------------------------------------------------------
// Kernel 2: SpMM scatter. One warp per edge: reads x[src] (512 floats =
// 128 float4, 4 per lane), scales by w, atomicAdd into g_h[dst, 512:1024].
// ---------------------------------------------------------------------------
__global__ void spmm_kernel(const float* __restrict__ x,
                            const float* __restrict__ ew,
                            const int*   __restrict__ src,
                            const int*   __restrict__ dst,
                            int E)
{
    int w    = (blockIdx.x * blockDim.x + threadIdx.x) >> 5;
    int lane = threadIdx.x & 31;
    if (w >= E) return;

    int   s  = __ldg(src + w);
    int   d  = __ldg(dst + w);
    float wt = __ldg(ew + w);

    const float4* xs  = (const float4*)(x + (long long)s * IN_DIM);
    float*        out = g_h + (long long)d * (2 * IN_DIM) + IN_DIM;

#pragma unroll
    for (int i = 0; i < 4; i++) {
        int idx = lane + 32 * i;
        float4 v = __ldg(xs + idx);
        int c = idx * 4;
        atomicAdd(out + c + 0, wt * v.x);
        atomicAdd(out + c + 1, wt * v.y);
        atomicAdd(out + c + 2, wt * v.z);
        atomicAdd(out + c + 3, wt * v.w);
    }
}

// ---------------------------------------------------------------------------
// Kernel 3: fused SGEMM + bias (+ optional ReLU).
//   C[M,Nc] = act(A[M,K] @ B[K,Nc] + bias)
// BM=BN=128, BK=16, 256 threads, 8x8 accumulator per thread, register
// double-buffering of the next global tile over the smem-compute phase.
// M may be ragged (50000); K, Nc are multiples of 16/128 here.
// ---------------------------------------------------------------------------
template <bool RELU>
__global__ void __launch_bounds__(256)
sgemm_bias(const float* __restrict__ A, const float* __restrict__ B,
           const float* __restrict__ bias, float* __restrict__ C,
           int M, int K, int Nc)
{
    const int BK = 16;
    __shared__ float As[BK][128];   // A transposed: As[k][m]
    __shared__ float Bs[BK][128];   // Bs[k][n]

    const int tid = threadIdx.x;
    const int bm  = blockIdx.y * 128;
    const int bn  = blockIdx.x * 128;

    const int tx = (tid & 15) * 8;   // col offset within BN
    const int ty = (tid >> 4) * 8;   // row offset within BM

    // A-tile load mapping: 128 rows x 16 cols = 512 float4; 2 per thread
    const int ar = tid >> 2;         // 0..63 (rows ar and ar+64)
    const int af = tid & 3;          // which float4 within the 16-col row
    // B-tile load mapping: 16 rows x 128 cols = 512 float4; 2 per thread
    const int br = tid >> 5;         // 0..7 (rows br and br+8)
    const int bc = tid & 31;         // float4 column

    float acc[8][8];
#pragma unroll
    for (int i = 0; i < 8; i++)
#pragma unroll
        for (int j = 0; j < 8; j++) acc[i][j] = 0.f;

    const int r0 = bm + ar;
    const int r1 = bm + ar + 64;
    const float4 zero4 = make_float4(0.f, 0.f, 0.f, 0.f);

    // --- prefetch tile t=0 into registers ---
    float4 a0 = (r0 < M) ? *(const float4*)(A + (long long)r0 * K + af * 4) : zero4;
    float4 a1 = (r1 < M) ? *(const float4*)(A + (long long)r1 * K + af * 4) : zero4;
    float4 b0 = *(const float4*)(B + (long long)br       * Nc + bn + bc * 4);
    float4 b1 = *(const float4*)(B + (long long)(br + 8) * Nc + bn + bc * 4);

    // store tile 0 into smem
    As[af * 4 + 0][ar]      = a0.x; As[af * 4 + 1][ar]      = a0.y;
    As[af * 4 + 2][ar]      = a0.z; As[af * 4 + 3][ar]      = a0.w;
    As[af * 4 + 0][ar + 64] = a1.x; As[af * 4 + 1][ar + 64] = a1.y;
    As[af * 4 + 2][ar + 64] = a1.z; As[af * 4 + 3][ar + 64] = a1.w;
    *(float4*)&Bs[br][bc * 4]     = b0;
    *(float4*)&Bs[br + 8][bc * 4] = b1;

    for (int t = 0; t < K; t += BK) {
        __syncthreads();

        const bool more = (t + BK) < K;
        if (more) {
            const int tn = t + BK;
            a0 = (r0 < M) ? *(const float4*)(A + (long long)r0 * K + tn + af * 4) : zero4;
            a1 = (r1 < M) ? *(const float4*)(A + (long long)r1 * K + tn + af * 4) : zero4;
            b0 = *(const float4*)(B + (long long)(tn + br)     * Nc + bn + bc * 4);
            b1 = *(const float4*)(B + (long long)(tn + br + 8) * Nc + bn + bc * 4);
        }

#pragma unroll
        for (int kk = 0; kk < BK; kk++) {
            float areg[8], breg[8];
            *(float4*)&areg[0] = *(const float4*)&As[kk][ty];
            *(float4*)&areg[4] = *(const float4*)&As[kk][ty + 4];
            *(float4*)&breg[0] = *(const float4*)&Bs[kk][tx];
            *(float4*)&breg[4] = *(const float4*)&Bs[kk][tx + 4];
#pragma unroll
            for (int i = 0; i < 8; i++)
#pragma unroll
                for (int j = 0; j < 8; j++)
                    acc[i][j] = fmaf(areg[i], breg[j], acc[i][j]);
        }

        __syncthreads();
        if (more) {
            As[af * 4 + 0][ar]      = a0.x; As[af * 4 + 1][ar]      = a0.y;
            As[af * 4 + 2][ar]      = a0.z; As[af * 4 + 3][ar]      = a0.w;
            As[af * 4 + 0][ar + 64] = a1.x; As[af * 4 + 1][ar + 64] = a1.y;
            As[af * 4 + 2][ar + 64] = a1.z; As[af * 4 + 3][ar + 64] = a1.w;
            *(float4*)&Bs[br][bc * 4]     = b0;
            *(float4*)&Bs[br + 8][bc * 4] = b1;
        }
    }

    // --- epilogue: bias (+ReLU), guarded vectorized stores ---
    float bi[8];
    *(float4*)&bi[0] = *(const float4*)(bias + bn + tx);
    *(float4*)&bi[4] = *(const float4*)(bias + bn + tx + 4);

#pragma unroll
    for (int i = 0; i < 8; i++) {
        const int row = bm + ty + i;
        if (row >= M) continue;
#pragma unroll
        for (int j = 0; j < 8; j++) {
            float v = acc[i][j] + bi[j];
            if (RELU) v = fmaxf(v, 0.f);
            acc[i][j] = v;
        }
        *(float4*)(C + (long long)row * Nc + bn + tx)     = *(float4*)&acc[i][0];
        *(float4*)(C + (long long)row * Nc + bn + tx + 4) = *(float4*)&acc[i][4];
    }
}

// ---------------------------------------------------------------------------
// Launcher
// ---------------------------------------------------------------------------
extern "C" void kernel_launch(void* const* d_in, const int* in_sizes, int n_in,
                              void* d_out, int out_size)
{
    const float* x    = (const float*)d_in[0];
    const float* ew   = (const float*)d_in[1];
    const float* W1   = (const float*)d_in[2];
    const float* b1   = (const float*)d_in[3];
    const float* W2   = (const float*)d_in[4];
    const float* b2   = (const float*)d_in[5];
    const float* W3   = (const float*)d_in[6];
    const float* b3   = (const float*)d_in[7];
    const int*   esrc = (const int*)d_in[8];
    const int*   edst = (const int*)d_in[9];
    float*       out  = (float*)d_out;

    const int n = in_sizes[0] / IN_DIM;   // 50000
    const int E = in_sizes[1];            // 1.6M

    float *h, *h1, *h2;
    cudaGetSymbolAddress((void**)&h,  g_h);
    cudaGetSymbolAddress((void**)&h1, g_h1);
    cudaGetSymbolAddress((void**)&h2, g_h2);

    // 1) h = [x, 0]
    {
        long long total = (long long)n * 256;
        int blocks = (int)((total + 255) / 256);
        init_h_kernel<<<blocks, 256>>>(x, n);
    }
    // 2) h[:, 512:] += scatter-add of w_e * x[src_e]
    {
        int blocks = (E + 7) / 8;   // 8 warps/block, 1 warp/edge
        spmm_kernel<<<blocks, 256>>>(x, ew, esrc, edst, E);
    }
    // 3) h1 = relu(h @ W1 + b1)
    {
        dim3 grid(HDIM / 128, (n + 127) / 128);
        sgemm_bias<true><<<grid, 256>>>(h, W1, b1, h1, n, 2 * IN_DIM, HDIM);
    }
    // 4) h2 = relu(h1 @ W2 + b2)
    {
        dim3 grid(HDIM / 128, (n + 127) / 128);
        sgemm_bias<true><<<grid, 256>>>(h1, W2, b2, h2, n, HDIM, HDIM);
    }
    // 5) out = h2 @ W3 + b3
    {
        dim3 grid(OUT_DIM / 128, (n + 127) / 128);
        sgemm_bias<false><<<grid, 256>>>(h2, W3, b3, out, n, HDIM, OUT_DIM);
    }
}

// round 5
// speedup vs baseline: 2.3610x; 2.3610x over previous
#include <cuda_runtime.h>
#include <cuda_bf16.h>
#include <cstdint>
#include <cstddef>

#define N_NODES 50000
#define IN_DIM  512
#define HDIM    2048
#define OUT_DIM 512
#define KP1     3072     // 3 * 1024
#define KP2     6144     // 3 * 2048

// ---------------------------------------------------------------------------
// Device-global scratch (allocation-free per harness rules)
// ---------------------------------------------------------------------------
__device__ float         g_h  [(size_t)N_NODES * 1024];        // [x | agg] fp32
__device__ __nv_bfloat16 g_A1 [(size_t)N_NODES * KP1];         // packed split of h
__device__ __nv_bfloat16 g_A2 [(size_t)N_NODES * KP2];         // packed split of layer-1 out
__device__ __nv_bfloat16 g_A3 [(size_t)N_NODES * KP2];         // packed split of layer-2 out
__device__ __nv_bfloat16 g_W1t[(size_t)HDIM    * KP1];         // [N,3K] packed transposed
__device__ __nv_bfloat16 g_W2t[(size_t)HDIM    * KP2];
__device__ __nv_bfloat16 g_W3t[(size_t)OUT_DIM * KP2];

// ---------------------------------------------------------------------------
// PTX helpers (base compute_103 features only: cp.async / ldmatrix / mma.sync)
// ---------------------------------------------------------------------------
__device__ __forceinline__ uint32_t smem_u32(const void* p) {
    uint32_t a;
    asm("{ .reg .u64 t; cvta.to.shared.u64 t, %1; cvt.u32.u64 %0, t; }"
        : "=r"(a) : "l"(p));
    return a;
}
__device__ __forceinline__ void cp_async16(uint32_t dst, const void* src, bool pred) {
    int sz = pred ? 16 : 0;
    asm volatile("cp.async.cg.shared.global [%0], [%1], 16, %2;"
                 :: "r"(dst), "l"(src), "r"(sz));
}
__device__ __forceinline__ void cp_commit() { asm volatile("cp.async.commit_group;"); }
__device__ __forceinline__ void cp_wait1()  { asm volatile("cp.async.wait_group 1;" ::: "memory"); }
__device__ __forceinline__ void cp_wait0()  { asm volatile("cp.async.wait_group 0;" ::: "memory"); }

__device__ __forceinline__ void ldmx4(uint32_t& r0, uint32_t& r1, uint32_t& r2, uint32_t& r3,
                                      uint32_t addr) {
    asm volatile("ldmatrix.sync.aligned.m8n8.x4.shared.b16 {%0,%1,%2,%3}, [%4];"
                 : "=r"(r0), "=r"(r1), "=r"(r2), "=r"(r3) : "r"(addr));
}
__device__ __forceinline__ void mma16816(float* c, const uint32_t* a, const uint32_t* b) {
    asm volatile(
        "mma.sync.aligned.m16n8k16.row.col.f32.bf16.bf16.f32 "
        "{%0,%1,%2,%3}, {%4,%5,%6,%7}, {%8,%9}, {%0,%1,%2,%3};"
        : "+f"(c[0]), "+f"(c[1]), "+f"(c[2]), "+f"(c[3])
        : "r"(a[0]), "r"(a[1]), "r"(a[2]), "r"(a[3]), "r"(b[0]), "r"(b[1]));
}
__device__ __forceinline__ uint32_t swz(uint32_t off) {       // SW128 swizzle
    return off ^ ((off >> 3) & 0x70);
}

// ---------------------------------------------------------------------------
// Kernel 1: h = [x, 0]
// ---------------------------------------------------------------------------
__global__ void init_h_kernel(const float* __restrict__ x, int n)
{
    long long i = (long long)blockIdx.x * blockDim.x + threadIdx.x;
    long long total = (long long)n * 256;
    if (i >= total) return;
    int row = (int)(i >> 8);
    int c4  = (int)(i & 255);
    float4 v = make_float4(0.f, 0.f, 0.f, 0.f);
    if (c4 < 128) v = ((const float4*)x)[(long long)row * 128 + c4];
    ((float4*)g_h)[i] = v;
}

// ---------------------------------------------------------------------------
// Kernel 2: SpMM scatter (warp per edge, fp32 atomics into right half of h)
// ---------------------------------------------------------------------------
__global__ void spmm_kernel(const float* __restrict__ x, const float* __restrict__ ew,
                            const int* __restrict__ src, const int* __restrict__ dst, int E)
{
    int w    = (blockIdx.x * blockDim.x + threadIdx.x) >> 5;
    int lane = threadIdx.x & 31;
    if (w >= E) return;
    int   s  = __ldg(src + w);
    int   d  = __ldg(dst + w);
    float wt = __ldg(ew + w);
    const float4* xs = (const float4*)(x + (long long)s * IN_DIM);
    float* out = g_h + (long long)d * 1024 + IN_DIM;
#pragma unroll
    for (int i = 0; i < 4; i++) {
        int idx = lane + 32 * i;
        float4 v = __ldg(xs + idx);
        int c = idx * 4;
        atomicAdd(out + c + 0, wt * v.x);
        atomicAdd(out + c + 1, wt * v.y);
        atomicAdd(out + c + 2, wt * v.z);
        atomicAdd(out + c + 3, wt * v.w);
    }
}

// ---------------------------------------------------------------------------
// Kernel 3: split-convert h (fp32 [M,1024]) -> A1 packed bf16 [M, 3072]
// layout [hi | hi | lo]
// ---------------------------------------------------------------------------
__global__ void convert_h_kernel(int M)
{
    size_t i = (size_t)blockIdx.x * blockDim.x + threadIdx.x;   // float2 units
    size_t total = (size_t)M * 512;
    if (i >= total) return;
    int m  = (int)(i >> 9);
    int k2 = (int)(i & 511);
    float2 v = ((const float2*)(g_h + (size_t)m * 1024))[k2];
    __nv_bfloat16 h0 = __float2bfloat16(v.x), h1 = __float2bfloat16(v.y);
    __nv_bfloat16 l0 = __float2bfloat16(v.x - __bfloat162float(h0));
    __nv_bfloat16 l1 = __float2bfloat16(v.y - __bfloat162float(h1));
    __nv_bfloat162 hh = __halves2bfloat162(h0, h1);
    __nv_bfloat162 ll = __halves2bfloat162(l0, l1);
    __nv_bfloat162* row = (__nv_bfloat162*)(g_A1 + (size_t)m * KP1);
    row[k2]        = hh;
    row[512 + k2]  = hh;
    row[1024 + k2] = ll;
}

// ---------------------------------------------------------------------------
// Kernel 4: split-convert + transpose weights: W [K,N] fp32 -> Wt [N, 3K] bf16
// layout [hi | lo | hi]  (pairs with A's [hi | hi | lo])
// ---------------------------------------------------------------------------
__global__ void convert_w_kernel(const float* __restrict__ W, __nv_bfloat16* __restrict__ Wt,
                                 int K, int N)
{
    size_t i = (size_t)blockIdx.x * blockDim.x + threadIdx.x;
    if (i >= (size_t)K * N) return;
    int k = (int)(i / N);
    int n = (int)(i - (size_t)k * N);
    float v = W[i];
    __nv_bfloat16 hi = __float2bfloat16(v);
    __nv_bfloat16 lo = __float2bfloat16(v - __bfloat162float(hi));
    size_t r = (size_t)n * (3 * (size_t)K);
    Wt[r + k]         = hi;
    Wt[r + K + k]     = lo;
    Wt[r + 2 * K + k] = hi;
}

// ---------------------------------------------------------------------------
// Kernel 5: HMMA (mma.sync bf16) GEMM.
//   C[M,Nc] = act(A[M,Kp] @ Bt[Nc,Kp]^T + bias)
// BM=BN=128, BK=64, 8 warps (warp tile 32x64), cp.async double buffer,
// SW128-swizzled smem, ldmatrix fragment loads.
// PACK: write split-bf16 packed output [hi|hi|lo] with row stride 3*Nc.
// ---------------------------------------------------------------------------
#define SM_A0 0
#define SM_B0 16384
#define SM_A1 32768
#define SM_B1 49152
#define SMEM_BYTES 65536

__device__ __forceinline__ void load_tile_A(const __nv_bfloat16* A, int bm, int M, int Kp,
                                            int kt, uint32_t sdst, int tid)
{
#pragma unroll
    for (int i = 0; i < 4; i++) {
        int c = tid + i * 256;              // 0..1023 16B-chunks
        int row = c >> 3, c16 = c & 7;
        int rm = bm + row;
        bool ok = rm < M;
        int rs = ok ? rm : (M - 1);
        const void* src = (const char*)(A + (size_t)rs * Kp + kt * 64) + c16 * 16;
        cp_async16(sdst + swz(row * 128 + c16 * 16), src, ok);
    }
}
__device__ __forceinline__ void load_tile_B(const __nv_bfloat16* Bt, int bn, int Kp,
                                            int kt, uint32_t sdst, int tid)
{
#pragma unroll
    for (int i = 0; i < 4; i++) {
        int c = tid + i * 256;              // 0..1023
        int row = c >> 3, c16 = c & 7;
        const void* src = (const char*)(Bt + (size_t)(bn + row) * Kp + kt * 64) + c16 * 16;
        cp_async16(sdst + swz(row * 128 + c16 * 16), src, true);
    }
}

template <bool RELU, bool PACK>
__global__ void __launch_bounds__(256, 2)
hmma_gemm(const __nv_bfloat16* __restrict__ A, const __nv_bfloat16* __restrict__ Bt,
          const float* __restrict__ bias, void* __restrict__ Cout,
          int M, int Kp, int Nc)
{
    extern __shared__ __align__(1024) char smem[];
    const uint32_t sb = smem_u32(smem);
    const int tid  = threadIdx.x;
    const int wid  = tid >> 5;
    const int lane = tid & 31;
    const int warp_m = wid & 3;        // 4 warps along M (32 rows each)
    const int warp_n = wid >> 2;       // 2 warps along N (64 cols each)
    const int bm = blockIdx.y * 128;
    const int bn = blockIdx.x * 128;

    const int j = lane >> 3;           // ldmatrix matrix index 0..3
    const int r = lane & 7;            // row within 8x8 matrix

    float acc[2][8][4];
#pragma unroll
    for (int mt = 0; mt < 2; mt++)
#pragma unroll
        for (int nt = 0; nt < 8; nt++)
#pragma unroll
            for (int q = 0; q < 4; q++) acc[mt][nt][q] = 0.f;

    const int T = Kp / 64;

    load_tile_A(A, bm, M, Kp, 0, sb + SM_A0, tid);
    load_tile_B(Bt, bn, Kp, 0, sb + SM_B0, tid);
    cp_commit();
    load_tile_A(A, bm, M, Kp, 1, sb + SM_A1, tid);
    load_tile_B(Bt, bn, Kp, 1, sb + SM_B1, tid);
    cp_commit();

    // per-thread ldmatrix address components (byte offsets within tile)
    // A matrices for m16k16 tile (mt): [m0,k0],[m0+8,k0],[m0,k8],[m0+8,k8]
    const int amrow0 = warp_m * 32 + (j & 1) * 8 + r;   // + mt*16
    const int akoff  = (j >> 1) * 16;                   // + ks*32 bytes
    // B matrices for n16k16 block (nb): [n0,k0],[n0,k8],[n0+8,k0],[n0+8,k8]
    const int bnrow0 = warp_n * 64 + (j >> 1) * 8 + r;  // + nb*16
    const int bkoff  = (j & 1) * 16;                    // + ks*32 bytes

    for (int kt = 0; kt < T; kt++) {
        const int s = kt & 1;
        if (kt == T - 1) cp_wait0(); else cp_wait1();
        __syncthreads();
        const uint32_t sA = sb + (s ? SM_A1 : SM_A0);
        const uint32_t sB = sb + (s ? SM_B1 : SM_B0);

#pragma unroll
        for (int ks = 0; ks < 4; ks++) {
            uint32_t a[2][4], b[8][2];
#pragma unroll
            for (int mt = 0; mt < 2; mt++) {
                uint32_t addr = sA + swz((uint32_t)(amrow0 + mt * 16) * 128 +
                                         (uint32_t)(ks * 32 + akoff));
                ldmx4(a[mt][0], a[mt][1], a[mt][2], a[mt][3], addr);
            }
#pragma unroll
            for (int nb = 0; nb < 4; nb++) {
                uint32_t addr = sB + swz((uint32_t)(bnrow0 + nb * 16) * 128 +
                                         (uint32_t)(ks * 32 + bkoff));
                uint32_t t0, t1, t2, t3;
                ldmx4(t0, t1, t2, t3, addr);
                b[2 * nb][0] = t0; b[2 * nb][1] = t1;
                b[2 * nb + 1][0] = t2; b[2 * nb + 1][1] = t3;
            }
#pragma unroll
            for (int mt = 0; mt < 2; mt++)
#pragma unroll
                for (int nt = 0; nt < 8; nt++)
                    mma16816(acc[mt][nt], a[mt], b[nt]);
        }

        __syncthreads();
        if (kt + 2 < T) {
            load_tile_A(A, bm, M, Kp, kt + 2, sA, tid);
            load_tile_B(Bt, bn, Kp, kt + 2, sB, tid);
            cp_commit();
        }
    }

    // ------------------------- epilogue -------------------------
    const int row0 = bm + warp_m * 32;
    const int col0 = bn + warp_n * 64;
#pragma unroll
    for (int mt = 0; mt < 2; mt++) {
#pragma unroll
        for (int nt = 0; nt < 8; nt++) {
            const int gc = col0 + nt * 8 + 2 * (lane & 3);
            const float bi0 = __ldg(bias + gc);
            const float bi1 = __ldg(bias + gc + 1);
#pragma unroll
            for (int half = 0; half < 2; half++) {
                const int m = row0 + mt * 16 + (lane >> 2) + half * 8;
                if (m >= M) continue;
                float v0 = acc[mt][nt][half * 2 + 0] + bi0;
                float v1 = acc[mt][nt][half * 2 + 1] + bi1;
                if (RELU) { v0 = fmaxf(v0, 0.f); v1 = fmaxf(v1, 0.f); }
                if (PACK) {
                    __nv_bfloat16 h0 = __float2bfloat16(v0), h1 = __float2bfloat16(v1);
                    __nv_bfloat16 l0 = __float2bfloat16(v0 - __bfloat162float(h0));
                    __nv_bfloat16 l1 = __float2bfloat16(v1 - __bfloat162float(h1));
                    __nv_bfloat162 hh = __halves2bfloat162(h0, h1);
                    __nv_bfloat162 ll = __halves2bfloat162(l0, l1);
                    __nv_bfloat16* O = (__nv_bfloat16*)Cout;
                    const size_t base = (size_t)m * (3 * (size_t)Nc);
                    *(__nv_bfloat162*)(O + base + gc)          = hh;
                    *(__nv_bfloat162*)(O + base + Nc + gc)     = hh;
                    *(__nv_bfloat162*)(O + base + 2 * Nc + gc) = ll;
                } else {
                    float* O = (float*)Cout;
                    float2 v = make_float2(v0, v1);
                    *(float2*)(O + (size_t)m * Nc + gc) = v;
                }
            }
        }
    }
}

// ---------------------------------------------------------------------------
// Launcher
// ---------------------------------------------------------------------------
extern "C" void kernel_launch(void* const* d_in, const int* in_sizes, int n_in,
                              void* d_out, int out_size)
{
    const float* x    = (const float*)d_in[0];
    const float* ew   = (const float*)d_in[1];
    const float* W1   = (const float*)d_in[2];
    const float* b1   = (const float*)d_in[3];
    const float* W2   = (const float*)d_in[4];
    const float* b2   = (const float*)d_in[5];
    const float* W3   = (const float*)d_in[6];
    const float* b3   = (const float*)d_in[7];
    const int*   esrc = (const int*)d_in[8];
    const int*   edst = (const int*)d_in[9];

    const int n = in_sizes[0] / IN_DIM;   // 50000
    const int E = in_sizes[1];            // 1.6M

    __nv_bfloat16 *A1, *A2, *A3, *W1t, *W2t, *W3t;
    cudaGetSymbolAddress((void**)&A1,  g_A1);
    cudaGetSymbolAddress((void**)&A2,  g_A2);
    cudaGetSymbolAddress((void**)&A3,  g_A3);
    cudaGetSymbolAddress((void**)&W1t, g_W1t);
    cudaGetSymbolAddress((void**)&W2t, g_W2t);
    cudaGetSymbolAddress((void**)&W3t, g_W3t);

    cudaFuncSetAttribute(hmma_gemm<true, true>,
                         cudaFuncAttributeMaxDynamicSharedMemorySize, SMEM_BYTES);
    cudaFuncSetAttribute(hmma_gemm<false, false>,
                         cudaFuncAttributeMaxDynamicSharedMemorySize, SMEM_BYTES);

    // 1) h = [x, 0]
    {
        long long total = (long long)n * 256;
        init_h_kernel<<<(int)((total + 255) / 256), 256>>>(x, n);
    }
    // 2) scatter-add into h[:, 512:]
    spmm_kernel<<<(E + 7) / 8, 256>>>(x, ew, esrc, edst, E);

    // 3) operand conversions
    {
        size_t t = (size_t)n * 512;
        convert_h_kernel<<<(int)((t + 255) / 256), 256>>>(n);
    }
    convert_w_kernel<<<(1024 * 2048 + 255) / 256, 256>>>(W1, W1t, 1024, HDIM);
    convert_w_kernel<<<(2048 * 2048 + 255) / 256, 256>>>(W2, W2t, HDIM, HDIM);
    convert_w_kernel<<<(2048 * 512  + 255) / 256, 256>>>(W3, W3t, HDIM, OUT_DIM);

    const int gy = (n + 127) / 128;   // 391
    // 4) layer 1: A2 = pack(relu(A1 @ W1t^T + b1))
    hmma_gemm<true, true><<<dim3(HDIM / 128, gy), 256, SMEM_BYTES>>>(
        A1, W1t, b1, (void*)A2, n, KP1, HDIM);
    // 5) layer 2: A3 = pack(relu(A2 @ W2t^T + b2))
    hmma_gemm<true, true><<<dim3(HDIM / 128, gy), 256, SMEM_BYTES>>>(
        A2, W2t, b2, (void*)A3, n, KP2, HDIM);
    // 6) layer 3: out = A3 @ W3t^T + b3   (fp32)
    hmma_gemm<false, false><<<dim3(OUT_DIM / 128, gy), 256, SMEM_BYTES>>>(
        A3, W3t, b3, d_out, n, KP2, OUT_DIM);
}

// round 6
// speedup vs baseline: 2.9439x; 1.2469x over previous
#include <cuda_runtime.h>
#include <cuda_bf16.h>
#include <cstdint>
#include <cstddef>

#define N_NODES 50000
#define IN_DIM  512
#define HDIM    2048
#define OUT_DIM 512
#define KP1     3072     // 3 * 1024
#define KP2     6144     // 3 * 2048

// ---------------------------------------------------------------------------
// Device-global scratch (allocation-free per harness rules).
// float4-typed to guarantee 16B alignment for cp.async / red.v4.
// ---------------------------------------------------------------------------
__device__ float4 g_hv [(size_t)N_NODES * 256];                 // [x | agg] fp32 (1024 f/row)
__device__ float4 g_A1v[(size_t)N_NODES * KP1 / 8];             // packed split of h (bf16)
__device__ float4 g_A2v[(size_t)N_NODES * KP2 / 8];             // packed split of layer-1 out
__device__ float4 g_A3v[(size_t)N_NODES * KP2 / 8];             // packed split of layer-2 out
__device__ float4 g_W1tv[(size_t)HDIM    * KP1 / 8];            // [N,3K] packed transposed
__device__ float4 g_W2tv[(size_t)HDIM    * KP2 / 8];
__device__ float4 g_W3tv[(size_t)OUT_DIM * KP2 / 8];

// ---------------------------------------------------------------------------
// PTX helpers (base compute_103 features only: cp.async / ldmatrix / mma.sync)
// ---------------------------------------------------------------------------
__device__ __forceinline__ uint32_t smem_u32(const void* p) {
    uint32_t a;
    asm("{ .reg .u64 t; cvta.to.shared.u64 t, %1; cvt.u32.u64 %0, t; }"
        : "=r"(a) : "l"(p));
    return a;
}
__device__ __forceinline__ void cp_async16(uint32_t dst, const void* src, bool pred) {
    int sz = pred ? 16 : 0;
    asm volatile("cp.async.cg.shared.global [%0], [%1], 16, %2;"
                 :: "r"(dst), "l"(src), "r"(sz));
}
__device__ __forceinline__ void cp_commit() { asm volatile("cp.async.commit_group;"); }
__device__ __forceinline__ void cp_wait1()  { asm volatile("cp.async.wait_group 1;" ::: "memory"); }
__device__ __forceinline__ void cp_wait0()  { asm volatile("cp.async.wait_group 0;" ::: "memory"); }

__device__ __forceinline__ void ldmx4(uint32_t& r0, uint32_t& r1, uint32_t& r2, uint32_t& r3,
                                      uint32_t addr) {
    asm volatile("ldmatrix.sync.aligned.m8n8.x4.shared.b16 {%0,%1,%2,%3}, [%4];"
                 : "=r"(r0), "=r"(r1), "=r"(r2), "=r"(r3) : "r"(addr));
}
__device__ __forceinline__ void mma16816(float* c, const uint32_t* a, const uint32_t* b) {
    asm volatile(
        "mma.sync.aligned.m16n8k16.row.col.f32.bf16.bf16.f32 "
        "{%0,%1,%2,%3}, {%4,%5,%6,%7}, {%8,%9}, {%0,%1,%2,%3};"
        : "+f"(c[0]), "+f"(c[1]), "+f"(c[2]), "+f"(c[3])
        : "r"(a[0]), "r"(a[1]), "r"(a[2]), "r"(a[3]), "r"(b[0]), "r"(b[1]));
}
__device__ __forceinline__ void red_add_v4(float* p, float4 v) {
    asm volatile("red.global.add.v4.f32 [%0], {%1,%2,%3,%4};"
                 :: "l"(p), "f"(v.x), "f"(v.y), "f"(v.z), "f"(v.w) : "memory");
}
__device__ __forceinline__ uint32_t swz(uint32_t off) {       // SW128 swizzle
    return off ^ ((off >> 3) & 0x70);
}

// ---------------------------------------------------------------------------
// Kernel 1: h = [x, 0]
// ---------------------------------------------------------------------------
__global__ void init_h_kernel(const float* __restrict__ x, int n)
{
    long long i = (long long)blockIdx.x * blockDim.x + threadIdx.x;
    long long total = (long long)n * 256;
    if (i >= total) return;
    int row = (int)(i >> 8);
    int c4  = (int)(i & 255);
    float4 v = make_float4(0.f, 0.f, 0.f, 0.f);
    if (c4 < 128) v = ((const float4*)x)[(long long)row * 128 + c4];
    g_hv[i] = v;
}

// ---------------------------------------------------------------------------
// Kernel 2: SpMM scatter (warp per edge) — vectorized fp32 atomics (red.v4)
// ---------------------------------------------------------------------------
__global__ void spmm_kernel(const float* __restrict__ x, const float* __restrict__ ew,
                            const int* __restrict__ src, const int* __restrict__ dst, int E)
{
    int w    = (blockIdx.x * blockDim.x + threadIdx.x) >> 5;
    int lane = threadIdx.x & 31;
    if (w >= E) return;
    int   s  = __ldg(src + w);
    int   d  = __ldg(dst + w);
    float wt = __ldg(ew + w);
    const float4* xs = (const float4*)(x + (long long)s * IN_DIM);
    float4* out4 = g_hv + (long long)d * 256 + 128;   // right half (agg)
#pragma unroll
    for (int i = 0; i < 4; i++) {
        int idx = lane + 32 * i;
        float4 v = __ldg(xs + idx);
        float4 m = make_float4(wt * v.x, wt * v.y, wt * v.z, wt * v.w);
        red_add_v4((float*)(out4 + idx), m);
    }
}

// ---------------------------------------------------------------------------
// Kernel 3: split-convert h (fp32 [M,1024]) -> A1 packed bf16 [M, 3072]
// layout [hi | hi | lo]
// ---------------------------------------------------------------------------
__global__ void convert_h_kernel(int M)
{
    const float* g_h = (const float*)g_hv;
    __nv_bfloat16* g_A1 = (__nv_bfloat16*)g_A1v;
    size_t i = (size_t)blockIdx.x * blockDim.x + threadIdx.x;   // float2 units
    size_t total = (size_t)M * 512;
    if (i >= total) return;
    int m  = (int)(i >> 9);
    int k2 = (int)(i & 511);
    float2 v = ((const float2*)(g_h + (size_t)m * 1024))[k2];
    __nv_bfloat16 h0 = __float2bfloat16(v.x), h1 = __float2bfloat16(v.y);
    __nv_bfloat16 l0 = __float2bfloat16(v.x - __bfloat162float(h0));
    __nv_bfloat16 l1 = __float2bfloat16(v.y - __bfloat162float(h1));
    __nv_bfloat162 hh = __halves2bfloat162(h0, h1);
    __nv_bfloat162 ll = __halves2bfloat162(l0, l1);
    __nv_bfloat162* row = (__nv_bfloat162*)(g_A1 + (size_t)m * KP1);
    row[k2]        = hh;
    row[512 + k2]  = hh;
    row[1024 + k2] = ll;
}

// ---------------------------------------------------------------------------
// Kernel 4: split-convert + transpose weights via smem tile:
//   W [K,N] fp32 -> Wt [N, 3K] bf16, layout [hi | lo | hi]
// block (32,8), grid (N/32, K/32); coalesced reads and 64B-contig writes.
// ---------------------------------------------------------------------------
__global__ void convert_w_kernel(const float* __restrict__ W, __nv_bfloat16* __restrict__ Wt,
                                 int K, int N)
{
    __shared__ float tile[32][33];
    const int k0 = blockIdx.y * 32;
    const int n0 = blockIdx.x * 32;
    const int tx = threadIdx.x;
#pragma unroll
    for (int r = threadIdx.y; r < 32; r += 8)
        tile[r][tx] = W[(size_t)(k0 + r) * N + n0 + tx];
    __syncthreads();
#pragma unroll
    for (int r = threadIdx.y; r < 32; r += 8) {
        int n = n0 + r;
        int k = k0 + tx;
        float v = tile[tx][r];
        __nv_bfloat16 hi = __float2bfloat16(v);
        __nv_bfloat16 lo = __float2bfloat16(v - __bfloat162float(hi));
        size_t base = (size_t)n * (3 * (size_t)K);
        Wt[base + k]         = hi;
        Wt[base + K + k]     = lo;
        Wt[base + 2 * K + k] = hi;
    }
}

// ---------------------------------------------------------------------------
// Kernel 5: HMMA (mma.sync bf16) GEMM.
//   C[M,Nc] = act(A[M,Kp] @ Bt[Nc,Kp]^T + bias)
// BM=BN=128, BK=64, 8 warps (warp tile 32x64), 3-stage cp.async ring with a
// SINGLE __syncthreads per k-tile, SW128-swizzled smem, ldmatrix loads.
// PACK: write split-bf16 packed output [hi|hi|lo] with row stride 3*Nc.
// ---------------------------------------------------------------------------
#define STAGE_BYTES 32768           // 16KB A + 16KB B
#define SMEM_BYTES  (3 * STAGE_BYTES)

__device__ __forceinline__ void load_tile_A(const __nv_bfloat16* A, int bm, int M, int Kp,
                                            int kt, uint32_t sdst, int tid)
{
#pragma unroll
    for (int i = 0; i < 4; i++) {
        int c = tid + i * 256;              // 0..1023 16B-chunks
        int row = c >> 3, c16 = c & 7;
        int rm = bm + row;
        bool ok = rm < M;
        int rs = ok ? rm : (M - 1);
        const void* src = (const char*)(A + (size_t)rs * Kp + kt * 64) + c16 * 16;
        cp_async16(sdst + swz(row * 128 + c16 * 16), src, ok);
    }
}
__device__ __forceinline__ void load_tile_B(const __nv_bfloat16* Bt, int bn, int Kp,
                                            int kt, uint32_t sdst, int tid)
{
#pragma unroll
    for (int i = 0; i < 4; i++) {
        int c = tid + i * 256;              // 0..1023
        int row = c >> 3, c16 = c & 7;
        const void* src = (const char*)(Bt + (size_t)(bn + row) * Kp + kt * 64) + c16 * 16;
        cp_async16(sdst + swz(row * 128 + c16 * 16), src, true);
    }
}

template <bool RELU, bool PACK>
__global__ void __launch_bounds__(256, 2)
hmma_gemm(const __nv_bfloat16* __restrict__ A, const __nv_bfloat16* __restrict__ Bt,
          const float* __restrict__ bias, void* __restrict__ Cout,
          int M, int Kp, int Nc)
{
    extern __shared__ __align__(1024) char smem[];
    const uint32_t sb = smem_u32(smem);
    const int tid  = threadIdx.x;
    const int wid  = tid >> 5;
    const int lane = tid & 31;
    const int warp_m = wid & 3;        // 4 warps along M (32 rows each)
    const int warp_n = wid >> 2;       // 2 warps along N (64 cols each)
    const int bm = blockIdx.y * 128;
    const int bn = blockIdx.x * 128;

    const int j = lane >> 3;           // ldmatrix matrix index 0..3
    const int r = lane & 7;            // row within 8x8 matrix

    float acc[2][8][4];
#pragma unroll
    for (int mt = 0; mt < 2; mt++)
#pragma unroll
        for (int nt = 0; nt < 8; nt++)
#pragma unroll
            for (int q = 0; q < 4; q++) acc[mt][nt][q] = 0.f;

    const int T = Kp / 64;

    // prologue: stages 0,1
    load_tile_A(A, bm, M, Kp, 0, sb + 0 * STAGE_BYTES, tid);
    load_tile_B(Bt, bn, Kp, 0, sb + 0 * STAGE_BYTES + 16384, tid);
    cp_commit();
    load_tile_A(A, bm, M, Kp, 1, sb + 1 * STAGE_BYTES, tid);
    load_tile_B(Bt, bn, Kp, 1, sb + 1 * STAGE_BYTES + 16384, tid);
    cp_commit();

    // per-thread ldmatrix address components (byte offsets within tile)
    const int amrow0 = warp_m * 32 + (j & 1) * 8 + r;   // + mt*16
    const int akoff  = (j >> 1) * 16;                   // + ks*32 bytes
    const int bnrow0 = warp_n * 64 + (j >> 1) * 8 + r;  // + nb*16
    const int bkoff  = (j & 1) * 16;                    // + ks*32 bytes

    int stage = 0;
    for (int kt = 0; kt < T; kt++) {
        if (kt == T - 1) cp_wait0(); else cp_wait1();
        __syncthreads();
        const uint32_t sA = sb + stage * STAGE_BYTES;
        const uint32_t sB = sA + 16384;

#pragma unroll
        for (int ks = 0; ks < 4; ks++) {
            uint32_t a[2][4], b[8][2];
#pragma unroll
            for (int mt = 0; mt < 2; mt++) {
                uint32_t addr = sA + swz((uint32_t)(amrow0 + mt * 16) * 128 +
                                         (uint32_t)(ks * 32 + akoff));
                ldmx4(a[mt][0], a[mt][1], a[mt][2], a[mt][3], addr);
            }
#pragma unroll
            for (int nb = 0; nb < 4; nb++) {
                uint32_t addr = sB + swz((uint32_t)(bnrow0 + nb * 16) * 128 +
                                         (uint32_t)(ks * 32 + bkoff));
                uint32_t t0, t1, t2, t3;
                ldmx4(t0, t1, t2, t3, addr);
                b[2 * nb][0] = t0; b[2 * nb][1] = t1;
                b[2 * nb + 1][0] = t2; b[2 * nb + 1][1] = t3;
            }
#pragma unroll
            for (int mt = 0; mt < 2; mt++)
#pragma unroll
                for (int nt = 0; nt < 8; nt++)
                    mma16816(acc[mt][nt], a[mt], b[nt]);
        }

        // prefetch kt+2 into the stage read at iteration kt-1 (safe: all
        // threads are past the barrier above, i.e. done with kt-1)
        if (kt + 2 < T) {
            int ns = stage + 2; if (ns >= 3) ns -= 3;
            load_tile_A(A, bm, M, Kp, kt + 2, sb + ns * STAGE_BYTES, tid);
            load_tile_B(Bt, bn, Kp, kt + 2, sb + ns * STAGE_BYTES + 16384, tid);
            cp_commit();
        }
        if (++stage == 3) stage = 0;
    }

    // ------------------------- epilogue -------------------------
    const int row0 = bm + warp_m * 32;
    const int col0 = bn + warp_n * 64;
#pragma unroll
    for (int mt = 0; mt < 2; mt++) {
#pragma unroll
        for (int nt = 0; nt < 8; nt++) {
            const int gc = col0 + nt * 8 + 2 * (lane & 3);
            const float bi0 = __ldg(bias + gc);
            const float bi1 = __ldg(bias + gc + 1);
#pragma unroll
            for (int half = 0; half < 2; half++) {
                const int m = row0 + mt * 16 + (lane >> 2) + half * 8;
                if (m >= M) continue;
                float v0 = acc[mt][nt][half * 2 + 0] + bi0;
                float v1 = acc[mt][nt][half * 2 + 1] + bi1;
                if (RELU) { v0 = fmaxf(v0, 0.f); v1 = fmaxf(v1, 0.f); }
                if (PACK) {
                    __nv_bfloat16 h0 = __float2bfloat16(v0), h1 = __float2bfloat16(v1);
                    __nv_bfloat16 l0 = __float2bfloat16(v0 - __bfloat162float(h0));
                    __nv_bfloat16 l1 = __float2bfloat16(v1 - __bfloat162float(h1));
                    __nv_bfloat162 hh = __halves2bfloat162(h0, h1);
                    __nv_bfloat162 ll = __halves2bfloat162(l0, l1);
                    __nv_bfloat16* O = (__nv_bfloat16*)Cout;
                    const size_t base = (size_t)m * (3 * (size_t)Nc);
                    *(__nv_bfloat162*)(O + base + gc)          = hh;
                    *(__nv_bfloat162*)(O + base + Nc + gc)     = hh;
                    *(__nv_bfloat162*)(O + base + 2 * Nc + gc) = ll;
                } else {
                    float* O = (float*)Cout;
                    float2 v = make_float2(v0, v1);
                    *(float2*)(O + (size_t)m * Nc + gc) = v;
                }
            }
        }
    }
}

// ---------------------------------------------------------------------------
// Launcher
// ---------------------------------------------------------------------------
extern "C" void kernel_launch(void* const* d_in, const int* in_sizes, int n_in,
                              void* d_out, int out_size)
{
    const float* x    = (const float*)d_in[0];
    const float* ew   = (const float*)d_in[1];
    const float* W1   = (const float*)d_in[2];
    const float* b1   = (const float*)d_in[3];
    const float* W2   = (const float*)d_in[4];
    const float* b2   = (const float*)d_in[5];
    const float* W3   = (const float*)d_in[6];
    const float* b3   = (const float*)d_in[7];
    const int*   esrc = (const int*)d_in[8];
    const int*   edst = (const int*)d_in[9];

    const int n = in_sizes[0] / IN_DIM;   // 50000
    const int E = in_sizes[1];            // 1.6M

    __nv_bfloat16 *A1, *A2, *A3, *W1t, *W2t, *W3t;
    cudaGetSymbolAddress((void**)&A1,  g_A1v);
    cudaGetSymbolAddress((void**)&A2,  g_A2v);
    cudaGetSymbolAddress((void**)&A3,  g_A3v);
    cudaGetSymbolAddress((void**)&W1t, g_W1tv);
    cudaGetSymbolAddress((void**)&W2t, g_W2tv);
    cudaGetSymbolAddress((void**)&W3t, g_W3tv);

    cudaFuncSetAttribute(hmma_gemm<true, true>,
                         cudaFuncAttributeMaxDynamicSharedMemorySize, SMEM_BYTES);
    cudaFuncSetAttribute(hmma_gemm<false, false>,
                         cudaFuncAttributeMaxDynamicSharedMemorySize, SMEM_BYTES);

    // 1) h = [x, 0]
    {
        long long total = (long long)n * 256;
        init_h_kernel<<<(int)((total + 255) / 256), 256>>>(x, n);
    }
    // 2) scatter-add into h[:, 512:]
    spmm_kernel<<<(E + 7) / 8, 256>>>(x, ew, esrc, edst, E);

    // 3) operand conversions
    {
        size_t t = (size_t)n * 512;
        convert_h_kernel<<<(int)((t + 255) / 256), 256>>>(n);
    }
    convert_w_kernel<<<dim3(HDIM / 32, 1024 / 32), dim3(32, 8)>>>(W1, W1t, 1024, HDIM);
    convert_w_kernel<<<dim3(HDIM / 32, HDIM / 32), dim3(32, 8)>>>(W2, W2t, HDIM, HDIM);
    convert_w_kernel<<<dim3(OUT_DIM / 32, HDIM / 32), dim3(32, 8)>>>(W3, W3t, HDIM, OUT_DIM);

    const int gy = (n + 127) / 128;   // 391
    // 4) layer 1: A2 = pack(relu(A1 @ W1t^T + b1))
    hmma_gemm<true, true><<<dim3(HDIM / 128, gy), 256, SMEM_BYTES>>>(
        A1, W1t, b1, (void*)A2, n, KP1, HDIM);
    // 5) layer 2: A3 = pack(relu(A2 @ W2t^T + b2))
    hmma_gemm<true, true><<<dim3(HDIM / 128, gy), 256, SMEM_BYTES>>>(
        A2, W2t, b2, (void*)A3, n, KP2, HDIM);
    // 6) layer 3: out = A3 @ W3t^T + b3   (fp32)
    hmma_gemm<false, false><<<dim3(OUT_DIM / 128, gy), 256, SMEM_BYTES>>>(
        A3, W3t, b3, d_out, n, KP2, OUT_DIM);
}